// round 8
// baseline (speedup 1.0000x reference)
#include <cuda_runtime.h>
#include <cuda_bf16.h>
#include <cstdint>

// LinearMPC via mma.sync bf16 (split hi/lo), cluster-of-8 u-exchange.
// u <- clip(u - s*(uH + f)), 100 iters, B=2048, M=512, H symmetric.
// R8: 512 threads (16 warps, K-split) + ldmatrix fragment loads.

#define MD 512
#define BATCH 2048
#define ITERS 100
#define STEPC 0.01f
#define CLS 8
#define CB 128
#define NC 64
#define KC 64
#define NCHUNK 8
#define THREADS 512
#define HSTR 1040u
#define USTR 144u
#define SM_HH 0u
#define SM_HL 66560u      // 64*HSTR
#define SM_U  133120u     // 2*64*HSTR
#define UPLANE 18432u     // 128*USTR
#define UBUF   36864u
#define SMEM_TOTAL 206848 // SM_U + 2*UBUF

__device__ __align__(16) float         g_f [BATCH * MD];
__device__ __align__(16) __nv_bfloat16 g_uh[BATCH * MD];
__device__ __align__(16) __nv_bfloat16 g_ul[BATCH * MD];

__device__ __forceinline__ uint32_t smem_u32_of(const void* p) {
    uint32_t a;
    asm("{ .reg .u64 t; cvta.to.shared.u64 t, %1; cvt.u32.u64 %0, t; }"
        : "=r"(a) : "l"(p));
    return a;
}
__device__ __forceinline__ void ldm_x4(uint32_t* r, uint32_t addr) {
    asm volatile(
        "ldmatrix.sync.aligned.m8n8.x4.shared.b16 {%0,%1,%2,%3}, [%4];"
        : "=r"(r[0]), "=r"(r[1]), "=r"(r[2]), "=r"(r[3]) : "r"(addr));
}
__device__ __forceinline__ void cp16(uint32_t s, const void* g) {
    asm volatile("cp.async.cg.shared.global [%0], [%1], 16;" :: "r"(s), "l"(g));
}
__device__ __forceinline__ void cp_commit() {
    asm volatile("cp.async.commit_group;");
}
template <int N>
__device__ __forceinline__ void cp_wait() {
    asm volatile("cp.async.wait_group %0;" :: "n"(N));
}
__device__ __forceinline__ void cluster_sync() {
    asm volatile("barrier.cluster.arrive.aligned;" ::: "memory");
    asm volatile("barrier.cluster.wait.aligned;" ::: "memory");
}
__device__ __forceinline__ void mma4(float* d, const uint32_t* a,
                                     const uint32_t* b) {
    asm volatile(
        "mma.sync.aligned.m16n8k16.row.col.f32.bf16.bf16.f32 "
        "{%0,%1,%2,%3}, {%4,%5,%6,%7}, {%8,%9}, {%0,%1,%2,%3};"
        : "+f"(d[0]), "+f"(d[1]), "+f"(d[2]), "+f"(d[3])
        : "r"(a[0]), "r"(a[1]), "r"(a[2]), "r"(a[3]), "r"(b[0]), "r"(b[1]));
}
__device__ __forceinline__ uint32_t bfsplit_hi(float x, float& r) {
    __nv_bfloat16 h = __float2bfloat16(x);
    r = x - __bfloat162float(h);
    return (uint32_t)__bfloat16_as_ushort(h);
}
__device__ __forceinline__ float bf_lo(uint32_t v) {
    return __bfloat162float(__ushort_as_bfloat16((unsigned short)(v & 0xFFFF)));
}
__device__ __forceinline__ float bf_hi(uint32_t v) {
    return __bfloat162float(__ushort_as_bfloat16((unsigned short)(v >> 16)));
}
__device__ __forceinline__ float clamp1(float x) {
    return fminf(fmaxf(x, -1.0f), 1.0f);
}
__device__ __forceinline__ void split_store(float v0, float v1,
                                            __nv_bfloat16* ph,
                                            __nv_bfloat16* pl) {
    float q0, q1, z;
    uint32_t a0 = bfsplit_hi(v0, q0), a1 = bfsplit_hi(v1, q1);
    *(uint32_t*)ph = a0 | (a1 << 16);
    *(uint32_t*)pl = bfsplit_hi(q0, z) | (bfsplit_hi(q1, z) << 16);
}

// Prologue: f[b, k*8+i] = -2 * Phi[k] @ Q @ (xref[b,k] - xref[b,0])
__global__ void mpc_f_kernel(const float* __restrict__ xref,
                             const float* __restrict__ Phi,
                             const float* __restrict__ Q) {
    int b = blockIdx.x, k = threadIdx.x;
    const float* xr = xref + (size_t)b * 65 * 8;
    float dx[8], t[8];
#pragma unroll
    for (int l = 0; l < 8; l++) dx[l] = xr[k * 8 + l] - xr[l];
#pragma unroll
    for (int j = 0; j < 8; j++) {
        float s = 0.f;
#pragma unroll
        for (int l = 0; l < 8; l++) s = fmaf(Q[j * 8 + l], dx[l], s);
        t[j] = s;
    }
    const float* Pk = Phi + (size_t)k * 64;
#pragma unroll
    for (int i = 0; i < 8; i++) {
        float s = 0.f;
#pragma unroll
        for (int j = 0; j < 8; j++) s = fmaf(Pk[i * 8 + j], t[j], s);
        g_f[(size_t)b * MD + k * 8 + i] = -2.0f * s;
    }
}

__global__ void __cluster_dims__(CLS, 1, 1) __launch_bounds__(THREADS, 1)
mpc_mma_kernel(const float* __restrict__ Hm, float* __restrict__ out) {
    extern __shared__ char smem[];
    const uint32_t sb = smem_u32_of(smem);
    const int tid = threadIdx.x, lane = tid & 31;
    const int qr = lane >> 2, qc = lane & 3;
    const int w = tid >> 5;
    const int wm = w & 3, wn = (w >> 2) & 1, kg = w >> 3;
    uint32_t rank;
    asm("mov.u32 %0, %%cluster_ctarank;" : "=r"(rank));
    const int cbase = (int)(blockIdx.x >> 3) * CB;
    const int n0 = (int)rank * NC;

    // ---- Stage H rows [n0, n0+64) as bf16 hi/lo (resident all iterations).
    for (int i = tid * 4; i < NC * MD; i += THREADS * 4) {
        int n = i >> 9, k = i & (MD - 1);
        float4 h = *(const float4*)&Hm[(size_t)(n0 + n) * MD + k];
        float r0, r1, r2, r3, z;
        uint32_t h0 = bfsplit_hi(h.x, r0), h1 = bfsplit_hi(h.y, r1);
        uint32_t h2 = bfsplit_hi(h.z, r2), h3 = bfsplit_hi(h.w, r3);
        uint32_t l0 = bfsplit_hi(r0, z), l1 = bfsplit_hi(r1, z);
        uint32_t l2 = bfsplit_hi(r2, z), l3 = bfsplit_hi(r3, z);
        uint32_t off = (uint32_t)n * HSTR + (uint32_t)(k << 1);
        *(uint2*)(smem + SM_HH + off) = make_uint2(h0 | (h1 << 16), h2 | (h3 << 16));
        *(uint2*)(smem + SM_HL + off) = make_uint2(l0 | (l1 << 16), l2 | (l3 << 16));
    }

    // ---- ldmatrix per-lane base addresses.
    uint32_t aBase[2], bBase[2];
#pragma unroll
    for (int mf = 0; mf < 2; mf++) {
        int row = 32 * wm + 16 * mf + (lane & 7) + 8 * ((lane >> 3) & 1);
        aBase[mf] = sb + SM_U + (uint32_t)row * USTR + 16u * (lane >> 4)
                    + (uint32_t)kg * 64u;
    }
#pragma unroll
    for (int p = 0; p < 2; p++) {
        int row = 32 * wn + 8 * (2 * p + (lane >> 4)) + (lane & 7);
        bBase[p] = sb + (uint32_t)row * HSTR + 16u * ((lane >> 3) & 1)
                   + (uint32_t)kg * 64u;
    }

    // ---- Loader geometry (4 threads per batch row, 32B each).
    const int lrow = tid >> 2;
    const int qe = (tid & 3) * 16;
    const __nv_bfloat16* srcH = g_uh + (size_t)(cbase + lrow) * MD + qe;
    const __nv_bfloat16* srcL = g_ul + (size_t)(cbase + lrow) * MD + qe;
    const uint32_t ldst = sb + SM_U + (uint32_t)lrow * USTR + (uint32_t)(tid & 3) * 32u;

    // ---- Fragment coordinates (epilogue, group 0 only).
    const int colb = n0 + 32 * wn + 2 * qc;

    // ---- Initial update: u1 = clip(-s*f), store hi/lo.
    if (kg == 0) {
#pragma unroll
        for (int mf = 0; mf < 2; mf++) {
            int r0 = cbase + 32 * wm + 16 * mf + qr;
#pragma unroll
            for (int nf = 0; nf < 4; nf++) {
                size_t o0 = (size_t)r0 * MD + colb + 8 * nf;
                size_t o8 = (size_t)(r0 + 8) * MD + colb + 8 * nf;
                float2 f0 = *(const float2*)&g_f[o0];
                float2 f8 = *(const float2*)&g_f[o8];
                split_store(clamp1(-STEPC * f0.x), clamp1(-STEPC * f0.y),
                            &g_uh[o0], &g_ul[o0]);
                split_store(clamp1(-STEPC * f8.x), clamp1(-STEPC * f8.y),
                            &g_uh[o8], &g_ul[o8]);
            }
        }
    }
    __syncthreads();   // H staged

    for (int it = 1; it < ITERS; it++) {
        __threadfence();
        cluster_sync();   // all cluster CTAs' u stores visible

#pragma unroll
        for (int pc = 0; pc < 2; pc++) {   // prefetch chunks 0,1
            uint32_t d = ldst + (uint32_t)pc * UBUF;
            const __nv_bfloat16* h = srcH + pc * KC;
            const __nv_bfloat16* l = srcL + pc * KC;
            cp16(d, h); cp16(d + 16, h + 8);
            cp16(d + UPLANE, l); cp16(d + UPLANE + 16, l + 8);
            cp_commit();
        }

        float acc[32];
#pragma unroll
        for (int i = 0; i < 32; i++) acc[i] = 0.f;

#pragma unroll 1
        for (int kc = 0; kc < NCHUNK; kc++) {
            if (kc == NCHUNK - 1) cp_wait<0>(); else cp_wait<1>();
            __syncthreads();

            const uint32_t abuf = (uint32_t)(kc & 1) * UBUF;
            const uint32_t bko = (uint32_t)kc * 128u;
#pragma unroll
            for (int ks = 0; ks < 2; ks++) {
                uint32_t ah[2][4], al[2][4], bh[4][4], bl[4][4];
                ldm_x4(ah[0], aBase[0] + abuf + ks * 32);
                ldm_x4(ah[1], aBase[1] + abuf + ks * 32);
                ldm_x4(al[0], aBase[0] + abuf + UPLANE + ks * 32);
                ldm_x4(al[1], aBase[1] + abuf + UPLANE + ks * 32);
                ldm_x4(bh[0], bBase[0] + bko + ks * 32);            // nf0,nf1
                ldm_x4(bh[2], bBase[1] + bko + ks * 32);            // nf2,nf3
                ldm_x4(bl[0], bBase[0] + SM_HL + bko + ks * 32);
                ldm_x4(bl[2], bBase[1] + SM_HL + bko + ks * 32);
#pragma unroll
                for (int nf = 0; nf < 4; nf++) {
                    const uint32_t* Bh = (nf & 1) ? &bh[nf & 2][2] : &bh[nf & 2][0];
                    const uint32_t* Bl = (nf & 1) ? &bl[nf & 2][2] : &bl[nf & 2][0];
#pragma unroll
                    for (int mf = 0; mf < 2; mf++) {
                        float* d = &acc[(mf * 4 + nf) * 4];
                        mma4(d, ah[mf], Bh);
                        mma4(d, al[mf], Bh);
                        mma4(d, ah[mf], Bl);
                    }
                }
            }
            __syncthreads();
            if (kc + 2 < NCHUNK) {
                uint32_t d = ldst + (uint32_t)(kc & 1) * UBUF;
                const __nv_bfloat16* h = srcH + (kc + 2) * KC;
                const __nv_bfloat16* l = srcL + (kc + 2) * KC;
                cp16(d, h); cp16(d + 16, h + 8);
                cp16(d + UPLANE, l); cp16(d + UPLANE + 16, l + 8);
                cp_commit();
            }
        }

        // ---- K-split reduction: group1 -> smem (reuses u buf0), group0 adds.
        if (kg == 1) {
            char* r = smem + SM_U + (size_t)(tid - 256) * 144;
#pragma unroll
            for (int i = 0; i < 8; i++)
                *(float4*)(r + i * 16) = make_float4(acc[i * 4], acc[i * 4 + 1],
                                                    acc[i * 4 + 2], acc[i * 4 + 3]);
        }
        __syncthreads();
        if (kg == 0) {
            const char* r = smem + SM_U + (size_t)tid * 144;
#pragma unroll
            for (int i = 0; i < 8; i++) {
                float4 v = *(const float4*)(r + i * 16);
                acc[i * 4] += v.x; acc[i * 4 + 1] += v.y;
                acc[i * 4 + 2] += v.z; acc[i * 4 + 3] += v.w;
            }

            const bool last = (it == ITERS - 1);
#pragma unroll
            for (int mf = 0; mf < 2; mf++) {
                int r0 = cbase + 32 * wm + 16 * mf + qr;
#pragma unroll
                for (int nf = 0; nf < 4; nf++) {
                    size_t o0 = (size_t)r0 * MD + colb + 8 * nf;
                    size_t o8 = (size_t)(r0 + 8) * MD + colb + 8 * nf;
                    const float* a = &acc[(mf * 4 + nf) * 4];
                    float2 f0 = *(const float2*)&g_f[o0];
                    float2 f8 = *(const float2*)&g_f[o8];
                    uint32_t uh0 = *(const uint32_t*)&g_uh[o0];
                    uint32_t ul0 = *(const uint32_t*)&g_ul[o0];
                    uint32_t uh8 = *(const uint32_t*)&g_uh[o8];
                    uint32_t ul8 = *(const uint32_t*)&g_ul[o8];
                    float v0 = clamp1(fmaf(-STEPC, a[0] + f0.x, bf_lo(uh0) + bf_lo(ul0)));
                    float v1 = clamp1(fmaf(-STEPC, a[1] + f0.y, bf_hi(uh0) + bf_hi(ul0)));
                    float v2 = clamp1(fmaf(-STEPC, a[2] + f8.x, bf_lo(uh8) + bf_lo(ul8)));
                    float v3 = clamp1(fmaf(-STEPC, a[3] + f8.y, bf_hi(uh8) + bf_hi(ul8)));
                    if (last) {
                        *(float2*)&out[o0] = make_float2(v0, v1);
                        *(float2*)&out[o8] = make_float2(v2, v3);
                    } else {
                        split_store(v0, v1, &g_uh[o0], &g_ul[o0]);
                        split_store(v2, v3, &g_uh[o8], &g_ul[o8]);
                    }
                }
            }
        }
    }
}

extern "C" void kernel_launch(void* const* d_in, const int* in_sizes, int n_in,
                              void* d_out, int out_size) {
    // metadata order: x0, xref, H, Phi, Q
    const float* xref = (const float*)d_in[1];
    const float* H    = (const float*)d_in[2];
    const float* Phi  = (const float*)d_in[3];
    const float* Q    = (const float*)d_in[4];
    float* out        = (float*)d_out;

    cudaFuncSetAttribute(mpc_mma_kernel,
                         cudaFuncAttributeMaxDynamicSharedMemorySize, SMEM_TOTAL);

    mpc_f_kernel<<<BATCH, 64>>>(xref, Phi, Q);
    mpc_mma_kernel<<<(BATCH / CB) * CLS, THREADS, SMEM_TOTAL>>>(H, out);
}

// round 9
// speedup vs baseline: 2.0790x; 2.0790x over previous
#include <cuda_runtime.h>
#include <cuda_bf16.h>
#include <cstdint>

// LinearMPC via mma.sync bf16 (split hi/lo), cluster-of-8 u-exchange.
// u <- clip(u - s*(uH + f)), 100 iters, B=2048, M=512, H symmetric.
// R9: 256 thr, ldmatrix, 4-deep cp.async ring (KC=32), no threadfence.

#define MD 512
#define BATCH 2048
#define ITERS 100
#define STEPC 0.01f
#define CLS 8
#define CB 128
#define NC 64
#define KC 32
#define NCHUNK 16
#define THREADS 256
#define HSTR 1040u        // H smem row stride (1024 + 16)
#define ASTR 80u          // u-chunk row stride (64 + 16)
#define SM_HH 0u
#define SM_HL 66560u      // 64*HSTR
#define SM_U  133120u
#define UPLANE 10240u     // 128*ASTR
#define UBUF   20480u
#define SMEM_TOTAL 215040 // SM_U + 4*UBUF

__device__ __align__(16) float         g_f [BATCH * MD];
__device__ __align__(16) __nv_bfloat16 g_uh[BATCH * MD];
__device__ __align__(16) __nv_bfloat16 g_ul[BATCH * MD];

__device__ __forceinline__ uint32_t smem_u32_of(const void* p) {
    uint32_t a;
    asm("{ .reg .u64 t; cvta.to.shared.u64 t, %1; cvt.u32.u64 %0, t; }"
        : "=r"(a) : "l"(p));
    return a;
}
__device__ __forceinline__ void ldm_x4(uint32_t* r, uint32_t addr) {
    asm volatile(
        "ldmatrix.sync.aligned.m8n8.x4.shared.b16 {%0,%1,%2,%3}, [%4];"
        : "=r"(r[0]), "=r"(r[1]), "=r"(r[2]), "=r"(r[3]) : "r"(addr));
}
__device__ __forceinline__ void cp16(uint32_t s, const void* g) {
    asm volatile("cp.async.cg.shared.global [%0], [%1], 16;" :: "r"(s), "l"(g));
}
__device__ __forceinline__ void cp_commit() {
    asm volatile("cp.async.commit_group;");
}
template <int N>
__device__ __forceinline__ void cp_wait() {
    asm volatile("cp.async.wait_group %0;" :: "n"(N));
}
__device__ __forceinline__ void cluster_sync() {
    asm volatile("barrier.cluster.arrive.aligned;" ::: "memory");  // release
    asm volatile("barrier.cluster.wait.aligned;" ::: "memory");    // acquire
}
__device__ __forceinline__ void mma4(float* d, const uint32_t* a,
                                     const uint32_t* b) {
    asm volatile(
        "mma.sync.aligned.m16n8k16.row.col.f32.bf16.bf16.f32 "
        "{%0,%1,%2,%3}, {%4,%5,%6,%7}, {%8,%9}, {%0,%1,%2,%3};"
        : "+f"(d[0]), "+f"(d[1]), "+f"(d[2]), "+f"(d[3])
        : "r"(a[0]), "r"(a[1]), "r"(a[2]), "r"(a[3]), "r"(b[0]), "r"(b[1]));
}
__device__ __forceinline__ uint32_t bfsplit_hi(float x, float& r) {
    __nv_bfloat16 h = __float2bfloat16(x);
    r = x - __bfloat162float(h);
    return (uint32_t)__bfloat16_as_ushort(h);
}
__device__ __forceinline__ float clamp1(float x) {
    return fminf(fmaxf(x, -1.0f), 1.0f);
}
__device__ __forceinline__ void split_store(float v0, float v1,
                                            __nv_bfloat16* ph,
                                            __nv_bfloat16* pl) {
    float q0, q1, z;
    uint32_t a0 = bfsplit_hi(v0, q0), a1 = bfsplit_hi(v1, q1);
    __stcg((uint32_t*)ph, a0 | (a1 << 16));
    __stcg((uint32_t*)pl, bfsplit_hi(q0, z) | (bfsplit_hi(q1, z) << 16));
}

// Prologue: f[b, k*8+i] = -2 * Phi[k] @ Q @ (xref[b,k] - xref[b,0])
__global__ void mpc_f_kernel(const float* __restrict__ xref,
                             const float* __restrict__ Phi,
                             const float* __restrict__ Q) {
    int b = blockIdx.x, k = threadIdx.x;
    const float* xr = xref + (size_t)b * 65 * 8;
    float dx[8], t[8];
#pragma unroll
    for (int l = 0; l < 8; l++) dx[l] = xr[k * 8 + l] - xr[l];
#pragma unroll
    for (int j = 0; j < 8; j++) {
        float s = 0.f;
#pragma unroll
        for (int l = 0; l < 8; l++) s = fmaf(Q[j * 8 + l], dx[l], s);
        t[j] = s;
    }
    const float* Pk = Phi + (size_t)k * 64;
#pragma unroll
    for (int i = 0; i < 8; i++) {
        float s = 0.f;
#pragma unroll
        for (int j = 0; j < 8; j++) s = fmaf(Pk[i * 8 + j], t[j], s);
        g_f[(size_t)b * MD + k * 8 + i] = -2.0f * s;
    }
}

__global__ void __cluster_dims__(CLS, 1, 1) __launch_bounds__(THREADS, 1)
mpc_mma_kernel(const float* __restrict__ Hm, float* __restrict__ out) {
    extern __shared__ char smem[];
    const uint32_t sb = smem_u32_of(smem);
    const int tid = threadIdx.x, lane = tid & 31;
    const int qr = lane >> 2, qc = lane & 3;
    const int w = tid >> 5, wm = w & 3, wn = w >> 2;
    uint32_t rank;
    asm("mov.u32 %0, %%cluster_ctarank;" : "=r"(rank));
    const int cbase = (int)(blockIdx.x >> 3) * CB;
    const int n0 = (int)rank * NC;

    // ---- Stage H rows [n0, n0+64) as bf16 hi/lo (resident all iterations).
    for (int i = tid * 4; i < NC * MD; i += THREADS * 4) {
        int n = i >> 9, k = i & (MD - 1);
        float4 h = *(const float4*)&Hm[(size_t)(n0 + n) * MD + k];
        float r0, r1, r2, r3, z;
        uint32_t h0 = bfsplit_hi(h.x, r0), h1 = bfsplit_hi(h.y, r1);
        uint32_t h2 = bfsplit_hi(h.z, r2), h3 = bfsplit_hi(h.w, r3);
        uint32_t l0 = bfsplit_hi(r0, z), l1 = bfsplit_hi(r1, z);
        uint32_t l2 = bfsplit_hi(r2, z), l3 = bfsplit_hi(r3, z);
        uint32_t off = (uint32_t)n * HSTR + (uint32_t)(k << 1);
        *(uint2*)(smem + SM_HH + off) = make_uint2(h0 | (h1 << 16), h2 | (h3 << 16));
        *(uint2*)(smem + SM_HL + off) = make_uint2(l0 | (l1 << 16), l2 | (l3 << 16));
    }

    // ---- ldmatrix per-lane base addresses (validated in R8).
    uint32_t aBase[2], bBase[2];
#pragma unroll
    for (int mf = 0; mf < 2; mf++) {
        int row = 32 * wm + 16 * mf + (lane & 7) + 8 * ((lane >> 3) & 1);
        aBase[mf] = sb + SM_U + (uint32_t)row * ASTR + 16u * (lane >> 4);
    }
#pragma unroll
    for (int p = 0; p < 2; p++) {
        int row = 32 * wn + 8 * (2 * p + (lane >> 4)) + (lane & 7);
        bBase[p] = sb + (uint32_t)row * HSTR + 16u * ((lane >> 3) & 1);
    }

    // ---- Loader geometry: 2 threads per batch row, 32B (2 cp16) each plane.
    const int lrow = tid >> 1, lhalf = tid & 1;
    const __nv_bfloat16* srcH = g_uh + (size_t)(cbase + lrow) * MD + lhalf * 16;
    const __nv_bfloat16* srcL = g_ul + (size_t)(cbase + lrow) * MD + lhalf * 16;
    const uint32_t ldst = sb + SM_U + (uint32_t)lrow * ASTR + (uint32_t)lhalf * 32u;

    // ---- Per-thread fragment state: fs = s*f, u master.
    const int colb = n0 + 32 * wn + 2 * qc;
    float fsv[2][4][4], u_m[2][4][4];
#pragma unroll
    for (int mf = 0; mf < 2; mf++) {
        int r0 = cbase + 32 * wm + 16 * mf + qr;
#pragma unroll
        for (int nf = 0; nf < 4; nf++) {
            float2 a = *(const float2*)&g_f[(size_t)r0 * MD + colb + 8 * nf];
            float2 b = *(const float2*)&g_f[(size_t)(r0 + 8) * MD + colb + 8 * nf];
            fsv[mf][nf][0] = STEPC * a.x;  fsv[mf][nf][1] = STEPC * a.y;
            fsv[mf][nf][2] = STEPC * b.x;  fsv[mf][nf][3] = STEPC * b.y;
#pragma unroll
            for (int c = 0; c < 4; c++)
                u_m[mf][nf][c] = clamp1(-fsv[mf][nf][c]);
        }
    }
    // Store u1 (bf16 hi/lo) for the exchange.
#pragma unroll
    for (int mf = 0; mf < 2; mf++) {
        int r0 = cbase + 32 * wm + 16 * mf + qr;
#pragma unroll
        for (int nf = 0; nf < 4; nf++) {
            size_t o0 = (size_t)r0 * MD + colb + 8 * nf;
            size_t o8 = (size_t)(r0 + 8) * MD + colb + 8 * nf;
            split_store(u_m[mf][nf][0], u_m[mf][nf][1], &g_uh[o0], &g_ul[o0]);
            split_store(u_m[mf][nf][2], u_m[mf][nf][3], &g_uh[o8], &g_ul[o8]);
        }
    }
    __syncthreads();

    for (int it = 1; it < ITERS; it++) {
        cluster_sync();   // release/acquire: u stores visible cluster-wide

        // Prime 4 chunks.
#pragma unroll
        for (int pc = 0; pc < 4; pc++) {
            uint32_t d = ldst + (uint32_t)pc * UBUF;
            const __nv_bfloat16* h = srcH + pc * KC;
            const __nv_bfloat16* l = srcL + pc * KC;
            cp16(d, h); cp16(d + 16, h + 8);
            cp16(d + UPLANE, l); cp16(d + UPLANE + 16, l + 8);
            cp_commit();
        }

        float acc[2][4][4];
#pragma unroll
        for (int mf = 0; mf < 2; mf++)
#pragma unroll
            for (int nf = 0; nf < 4; nf++)
#pragma unroll
                for (int c = 0; c < 4; c++) acc[mf][nf][c] = 0.f;

#pragma unroll 1
        for (int kc = 0; kc < NCHUNK; kc++) {
            if (kc <= 12) cp_wait<3>();
            else if (kc == 13) cp_wait<2>();
            else if (kc == 14) cp_wait<1>();
            else cp_wait<0>();
            __syncthreads();   // chunk kc data visible to all

            const uint32_t abuf = (uint32_t)(kc & 3) * UBUF;
            const uint32_t bko = (uint32_t)kc * 64u;
#pragma unroll
            for (int ks = 0; ks < 2; ks++) {
                uint32_t ah[2][4], al[2][4], bh[2][4], bl[2][4];
                ldm_x4(ah[0], aBase[0] + abuf + ks * 32);
                ldm_x4(ah[1], aBase[1] + abuf + ks * 32);
                ldm_x4(al[0], aBase[0] + abuf + UPLANE + ks * 32);
                ldm_x4(al[1], aBase[1] + abuf + UPLANE + ks * 32);
                ldm_x4(bh[0], bBase[0] + bko + ks * 32);
                ldm_x4(bh[1], bBase[1] + bko + ks * 32);
                ldm_x4(bl[0], bBase[0] + SM_HL + bko + ks * 32);
                ldm_x4(bl[1], bBase[1] + SM_HL + bko + ks * 32);
#pragma unroll
                for (int nf = 0; nf < 4; nf++) {
                    const uint32_t* Bh = &bh[nf >> 1][(nf & 1) * 2];
                    const uint32_t* Bl = &bl[nf >> 1][(nf & 1) * 2];
#pragma unroll
                    for (int mf = 0; mf < 2; mf++) {
                        mma4(acc[mf][nf], ah[mf], Bh);
                        mma4(acc[mf][nf], al[mf], Bh);
                        mma4(acc[mf][nf], ah[mf], Bl);
                    }
                }
            }
            __syncthreads();   // all warps done with buffer kc&3
            if (kc + 4 < NCHUNK) {
                uint32_t d = ldst + (uint32_t)(kc & 3) * UBUF;
                const __nv_bfloat16* h = srcH + (kc + 4) * KC;
                const __nv_bfloat16* l = srcL + (kc + 4) * KC;
                cp16(d, h); cp16(d + 16, h + 8);
                cp16(d + UPLANE, l); cp16(d + UPLANE + 16, l + 8);
                cp_commit();
            }
        }

        // ---- u <- clip(u - s*acc - fs); store bf16 hi/lo (fp32 out on last).
        const bool last = (it == ITERS - 1);
#pragma unroll
        for (int mf = 0; mf < 2; mf++) {
            int r0 = cbase + 32 * wm + 16 * mf + qr;
#pragma unroll
            for (int nf = 0; nf < 4; nf++) {
#pragma unroll
                for (int c = 0; c < 4; c++) {
                    float t = fmaf(-STEPC, acc[mf][nf][c], u_m[mf][nf][c])
                              - fsv[mf][nf][c];
                    u_m[mf][nf][c] = clamp1(t);
                }
                size_t o0 = (size_t)r0 * MD + colb + 8 * nf;
                size_t o8 = (size_t)(r0 + 8) * MD + colb + 8 * nf;
                if (last) {
                    *(float2*)&out[o0] = make_float2(u_m[mf][nf][0], u_m[mf][nf][1]);
                    *(float2*)&out[o8] = make_float2(u_m[mf][nf][2], u_m[mf][nf][3]);
                } else {
                    split_store(u_m[mf][nf][0], u_m[mf][nf][1], &g_uh[o0], &g_ul[o0]);
                    split_store(u_m[mf][nf][2], u_m[mf][nf][3], &g_uh[o8], &g_ul[o8]);
                }
            }
        }
    }
}

extern "C" void kernel_launch(void* const* d_in, const int* in_sizes, int n_in,
                              void* d_out, int out_size) {
    // metadata order: x0, xref, H, Phi, Q
    const float* xref = (const float*)d_in[1];
    const float* H    = (const float*)d_in[2];
    const float* Phi  = (const float*)d_in[3];
    const float* Q    = (const float*)d_in[4];
    float* out        = (float*)d_out;

    cudaFuncSetAttribute(mpc_mma_kernel,
                         cudaFuncAttributeMaxDynamicSharedMemorySize, SMEM_TOTAL);

    mpc_f_kernel<<<BATCH, 64>>>(xref, Phi, Q);
    mpc_mma_kernel<<<(BATCH / CB) * CLS, THREADS, SMEM_TOTAL>>>(H, out);
}